// round 15
// baseline (speedup 1.0000x reference)
#include <cuda_runtime.h>
#include <cstdint>

#define ENTITYN 50000
#define EMBD    256
#define HIDD    256
#define BATCHN  64
#define LSEQ    256
#define NEDGE   800000

// ---------------- scratch (device globals: no allocation allowed) ----------------
__device__ float g_bufA[BATCHN * LSEQ * HIDD];
__device__ float g_bufB[BATCHN * LSEQ * HIDD];
__device__ float g_xi[BATCHN * LSEQ * 3 * HIDD];
__device__ float g_WihT[HIDD * 3 * HIDD];
__device__ float g_fc1WT[HIDD * HIDD];
__device__ float g_support[ENTITYN * HIDD];
__device__ float g_agg[ENTITYN * HIDD];
__device__ float g_hT[BATCHN * HIDD];
__device__ unsigned int g_sync[32 * 64];   // kept for prep compatibility (unused by GRU now)

#define SEL_EXT     0
#define SEL_BUFA    1
#define SEL_BUFB    2
#define SEL_XI      3
#define SEL_WIHT    4
#define SEL_SUPPORT 5

__device__ __forceinline__ float* selptr(int s, const void* ext) {
    switch (s) {
        case SEL_BUFA:    return g_bufA;
        case SEL_BUFB:    return g_bufB;
        case SEL_XI:      return g_xi;
        case SEL_WIHT:    return g_WihT;
        case SEL_SUPPORT: return g_support;
        default:          return (float*)ext;
    }
}

__device__ __forceinline__ uint32_t f2tf32(float x) {
    uint32_t u;
    asm("cvt.rna.tf32.f32 %0, %1;" : "=r"(u) : "f"(x));
    return u;
}

__device__ __forceinline__ void mma_tf32(float* c, const uint32_t* a,
                                         uint32_t b0, uint32_t b1) {
    asm volatile(
        "mma.sync.aligned.m16n8k8.row.col.f32.tf32.tf32.f32 "
        "{%0,%1,%2,%3}, {%4,%5,%6,%7}, {%8,%9}, {%0,%1,%2,%3};"
        : "+f"(c[0]), "+f"(c[1]), "+f"(c[2]), "+f"(c[3])
        : "r"(a[0]), "r"(a[1]), "r"(a[2]), "r"(a[3]), "r"(b0), "r"(b1));
}

// f32x2 packed-FMA helpers (proven on this toolchain in R14)
__device__ __forceinline__ unsigned long long packf2(float x, float y) {
    unsigned long long r;
    asm("mov.b64 %0, {%1, %2};"
        : "=l"(r) : "r"(__float_as_uint(x)), "r"(__float_as_uint(y)));
    return r;
}

__device__ __forceinline__ void ffma2(unsigned long long& acc,
                                      unsigned long long a,
                                      unsigned long long b) {
    asm("fma.rn.f32x2 %0, %1, %2, %0;" : "+l"(acc) : "l"(a), "l"(b));
}

__device__ __forceinline__ float unpack_sum(unsigned long long v) {
    uint32_t lo, hi;
    asm("mov.b64 {%0, %1}, %2;" : "=r"(lo), "=r"(hi) : "l"(v));
    return __uint_as_float(lo) + __uint_as_float(hi);
}

// ---------------- weight prep ----------------
__global__ void prep_kernel(const float* __restrict__ Wih,
                            const float* __restrict__ fc1W) {
    int stride = gridDim.x * blockDim.x;
    int t0 = blockIdx.x * blockDim.x + threadIdx.x;
    for (int i = t0; i < 32 * 64; i += stride) g_sync[i] = 0u;
    for (int i = t0; i < 256 * 768; i += stride) {
        int k = i / 768, n = i % 768;
        g_WihT[i] = Wih[n * 256 + k];
    }
    for (int i = t0; i < 256 * 256; i += stride) {
        int k = i / 256, j = i % 256;
        g_fc1WT[i] = fc1W[j * 256 + k];
    }
}

// ---------------- gated GNN path ----------------
__global__ void zero_agg_kernel(const float* __restrict__ eps) {
    if (eps[0] == 0.0f) return;
    int stride = gridDim.x * blockDim.x;
    for (int i = blockIdx.x * blockDim.x + threadIdx.x; i < ENTITYN * HIDD; i += stride)
        g_agg[i] = 0.0f;
}

__global__ void scatter_kernel(const int* __restrict__ esrc,
                               const int* __restrict__ edst,
                               const float* __restrict__ ew,
                               const float* __restrict__ eps) {
    if (eps[0] == 0.0f) return;
    long stride = (long)gridDim.x * blockDim.x;
    long total = (long)NEDGE * 64;
    for (long i = (long)blockIdx.x * blockDim.x + threadIdx.x; i < total; i += stride) {
        int e = (int)(i >> 6);
        int c = ((int)i & 63) * 4;
        int s = esrc[e], d = edst[e];
        float w = ew[e];
        const float4 v = *(const float4*)&g_support[(long)s * 256 + c];
        float* dst = &g_agg[(long)d * 256 + c];
        atomicAdd(dst + 0, v.x * w);
        atomicAdd(dst + 1, v.y * w);
        atomicAdd(dst + 2, v.z * w);
        atomicAdd(dst + 3, v.w * w);
    }
}

// ---------------- tf32 GEMM, block 256x128 (R13/R14-proven, untouched) ----------------
__global__ void __launch_bounds__(256, 1) mma_gemm_kernel(
    int selA, const void* Aext, long strideA,
    int selB, const void* Bext, long strideB,
    int selC, void* Cext, long strideC,
    const float* __restrict__ bias,
    const int* __restrict__ gidx,
    const float* __restrict__ gate,
    int M, int N, int K)
{
    if (gate != nullptr && gate[0] == 0.0f) return;
    const float* A = selptr(selA, Aext) + (long)blockIdx.z * strideA;
    const float* B = selptr(selB, Bext) + (long)blockIdx.z * strideB;
    float*       C = selptr(selC, Cext) + (long)blockIdx.z * strideC;

    __shared__ uint32_t As[256][20];
    __shared__ uint32_t Bs[16][136];

    const int tid  = threadIdx.x;
    const int wid  = tid >> 5, lane = tid & 31;
    const int g    = lane >> 2, t = lane & 3;
    const int wm   = wid >> 1, wn = wid & 1;
    const int m0   = blockIdx.y * 256, n0 = blockIdx.x * 128;

    long agrow[4];
#pragma unroll
    for (int i = 0; i < 4; i++) {
        int f = tid + i * 256;
        int m = m0 + (f >> 2);
        agrow[i] = (m < M) ? (gidx ? (long)gidx[m] : (long)m) : -1;
    }

    float acc[4][8][4];
#pragma unroll
    for (int mt = 0; mt < 4; mt++)
#pragma unroll
        for (int nt = 0; nt < 8; nt++)
#pragma unroll
            for (int q = 0; q < 4; q++) acc[mt][nt][q] = 0.0f;

    const int NCH = K >> 4;
    float4 ar[4], br[2];

#pragma unroll
    for (int i = 0; i < 4; i++) {
        int f = tid + i * 256;
        int k4 = (f & 3) * 4;
        ar[i] = (agrow[i] >= 0) ? *(const float4*)(A + agrow[i] * K + k4)
                                : make_float4(0.f, 0.f, 0.f, 0.f);
    }
#pragma unroll
    for (int i = 0; i < 2; i++) {
        int f = tid + i * 256;
        int kk = f >> 5, n4 = (f & 31) * 4;
        br[i] = *(const float4*)(B + (long)kk * N + n0 + n4);
    }

    for (int c = 0; c < NCH; c++) {
#pragma unroll
        for (int i = 0; i < 4; i++) {
            int f = tid + i * 256;
            int row = f >> 2, k4 = (f & 3) * 4;
            uint4 u = make_uint4(f2tf32(ar[i].x), f2tf32(ar[i].y),
                                 f2tf32(ar[i].z), f2tf32(ar[i].w));
            *(uint4*)&As[row][k4] = u;
        }
#pragma unroll
        for (int i = 0; i < 2; i++) {
            int f = tid + i * 256;
            int kk = f >> 5, n4 = (f & 31) * 4;
            uint4 u = make_uint4(f2tf32(br[i].x), f2tf32(br[i].y),
                                 f2tf32(br[i].z), f2tf32(br[i].w));
            *(uint4*)&Bs[kk][n4] = u;
        }
        __syncthreads();

        if (c + 1 < NCH) {
            int k0n = (c + 1) * 16;
#pragma unroll
            for (int i = 0; i < 4; i++) {
                int f = tid + i * 256;
                int k4 = (f & 3) * 4;
                ar[i] = (agrow[i] >= 0)
                        ? *(const float4*)(A + agrow[i] * K + k0n + k4)
                        : make_float4(0.f, 0.f, 0.f, 0.f);
            }
#pragma unroll
            for (int i = 0; i < 2; i++) {
                int f = tid + i * 256;
                int kk = f >> 5, n4 = (f & 31) * 4;
                br[i] = *(const float4*)(B + (long)(k0n + kk) * N + n0 + n4);
            }
        }

#pragma unroll
        for (int ks = 0; ks < 16; ks += 8) {
            uint32_t af[4][4];
#pragma unroll
            for (int mt = 0; mt < 4; mt++) {
                int r = wm * 64 + mt * 16 + g;
                af[mt][0] = As[r    ][ks + t];
                af[mt][1] = As[r + 8][ks + t];
                af[mt][2] = As[r    ][ks + t + 4];
                af[mt][3] = As[r + 8][ks + t + 4];
            }
#pragma unroll
            for (int nt = 0; nt < 8; nt++) {
                int cc = wn * 64 + nt * 8 + g;
                uint32_t b0 = Bs[ks + t    ][cc];
                uint32_t b1 = Bs[ks + t + 4][cc];
#pragma unroll
                for (int mt = 0; mt < 4; mt++)
                    mma_tf32(acc[mt][nt], af[mt], b0, b1);
            }
        }
        __syncthreads();
    }

#pragma unroll
    for (int mt = 0; mt < 4; mt++) {
        int r0 = m0 + wm * 64 + mt * 16 + g;
#pragma unroll
        for (int nt = 0; nt < 8; nt++) {
            int cc = n0 + wn * 64 + nt * 8 + 2 * t;
            float b0v = 0.f, b1v = 0.f;
            if (bias) { b0v = bias[cc]; b1v = bias[cc + 1]; }
            if (r0 < M) {
                float2 o = make_float2(acc[mt][nt][0] + b0v, acc[mt][nt][1] + b1v);
                *(float2*)(C + (long)r0 * N + cc) = o;
            }
            int r1 = r0 + 8;
            if (r1 < M) {
                float2 o = make_float2(acc[mt][nt][2] + b0v, acc[mt][nt][3] + b1v);
                *(float2*)(C + (long)r1 * N + cc) = o;
            }
        }
    }
}

// ---------------- eps mix (float4 fast path when eps == 0) ----------------
__global__ void mix_kernel(const int* __restrict__ cur,
                           const float* __restrict__ bg,
                           const float* __restrict__ eps) {
    float e = eps[0];
    int stride = gridDim.x * blockDim.x;
    int t0 = blockIdx.x * blockDim.x + threadIdx.x;
    if (e == 0.0f) {
        const float4* src = (const float4*)g_bufB;
        float4*       dst = (float4*)g_bufA;
        for (int i = t0; i < BATCHN * LSEQ * HIDD / 4; i += stride)
            dst[i] = src[i];
    } else {
        for (int i = t0; i < BATCHN * LSEQ * HIDD; i += stride) {
            int row = i >> 8, col = i & 255;
            int cn = cur[row];
            float a = g_agg[(long)cn * 256 + col] + bg[col];
            a = a > 0.0f ? a : 0.2f * a;
            g_bufA[i] = (1.0f - e) * g_bufB[i] + e * a;
        }
    }
}

// ---------------- GRU: 16 clusters x 8 CTAs. R14 compute body (f32x2),
// h exchanged via st.shared::cluster into peers' double-buffered smem,
// one barrier.cluster per step (arrive=release, wait=acquire). No global h,
// no counters.
__global__ void __launch_bounds__(384, 1) __cluster_dims__(8, 1, 1)
gru_cluster_kernel(const float* __restrict__ Whh,
                   const float* __restrict__ bhh) {
    __shared__ __align__(16) float hs[2][4][256];
    __shared__ float gh[96][4];
    __shared__ float sbl[96];

    const int tid = threadIdx.x;
    uint32_t rank;
    asm("mov.u32 %0, %%cluster_ctarank;" : "=r"(rank));
    const int cid = blockIdx.x >> 3;       // batch group 0..15
    const int j0  = (int)rank * 32;

    const int lrow = tid >> 2;             // 0..95
    const int kq   = tid & 3;              // lane's k-phase
    const int gate = lrow >> 5;
    const int jj   = lrow & 31;
    const int grow = gate * 256 + j0 + jj;

    // packed weights: lane kq owns k in {16*k4 + 4*kq .. +3}, stored as k-pairs
    unsigned long long w2[32];
    {
        const float* wrow = Whh + (long)grow * 256;
#pragma unroll
        for (int k4 = 0; k4 < 16; k4++) {
            float4 v = *(const float4*)(wrow + k4 * 16 + kq * 4);
            w2[k4 * 2 + 0] = packf2(v.x, v.y);
            w2[k4 * 2 + 1] = packf2(v.z, v.w);
        }
    }
    if (tid < 96) sbl[tid] = bhh[(tid >> 5) * 256 + j0 + (tid & 31)];

    const int ejj = tid >> 2, eb = tid & 3;   // epilogue mapping (tid<128)

    // zero both h buffers locally (h0 = 0); no remote writes needed for init
    for (int i = tid; i < 2 * 4 * 256; i += 384) ((float*)hs)[i] = 0.0f;
    __syncthreads();
    asm volatile("barrier.cluster.arrive.aligned;" ::: "memory");
    asm volatile("barrier.cluster.wait.aligned;"   ::: "memory");

    for (int t = 0; t < 256; t++) {
        const int p = t & 1;
        // prefetch xi (L2/DRAM latency hidden behind compute)
        float xr = 0.f, xz = 0.f, xn = 0.f;
        if (tid < 128) {
            const float* xb = g_xi + (((long)(cid * 4 + eb) * 256 + t) * 768);
            xr = xb[j0 + ejj];
            xz = xb[256 + j0 + ejj];
            xn = xb[512 + j0 + ejj];
        }

        // f32x2 k-pair accumulate; lane kq reads hs[p][b][16*k4 + 4*kq .. +3]
        unsigned long long a2[4] = {0ull, 0ull, 0ull, 0ull};
#pragma unroll
        for (int k4 = 0; k4 < 16; k4++) {
            const int ko = k4 * 16 + kq * 4;
            ulonglong2 h0 = *(const ulonglong2*)&hs[p][0][ko];
            ulonglong2 h1 = *(const ulonglong2*)&hs[p][1][ko];
            ulonglong2 h2 = *(const ulonglong2*)&hs[p][2][ko];
            ulonglong2 h3 = *(const ulonglong2*)&hs[p][3][ko];
            unsigned long long wa = w2[k4 * 2], wb = w2[k4 * 2 + 1];
            ffma2(a2[0], wa, h0.x); ffma2(a2[0], wb, h0.y);
            ffma2(a2[1], wa, h1.x); ffma2(a2[1], wb, h1.y);
            ffma2(a2[2], wa, h2.x); ffma2(a2[2], wb, h2.y);
            ffma2(a2[3], wa, h3.x); ffma2(a2[3], wb, h3.y);
        }
        float acc0 = unpack_sum(a2[0]);
        float acc1 = unpack_sum(a2[1]);
        float acc2 = unpack_sum(a2[2]);
        float acc3 = unpack_sum(a2[3]);
        acc0 += __shfl_xor_sync(0xFFFFFFFFu, acc0, 1);
        acc0 += __shfl_xor_sync(0xFFFFFFFFu, acc0, 2);
        acc1 += __shfl_xor_sync(0xFFFFFFFFu, acc1, 1);
        acc1 += __shfl_xor_sync(0xFFFFFFFFu, acc1, 2);
        acc2 += __shfl_xor_sync(0xFFFFFFFFu, acc2, 1);
        acc2 += __shfl_xor_sync(0xFFFFFFFFu, acc2, 2);
        acc3 += __shfl_xor_sync(0xFFFFFFFFu, acc3, 1);
        acc3 += __shfl_xor_sync(0xFFFFFFFFu, acc3, 2);
        if (kq == 0) {
            gh[lrow][0] = acc0; gh[lrow][1] = acc1;
            gh[lrow][2] = acc2; gh[lrow][3] = acc3;
        }
        __syncthreads();

        if (tid < 128) {
            float hr = gh[ejj][eb]      + sbl[ejj];
            float hz = gh[32 + ejj][eb] + sbl[32 + ejj];
            float hn = gh[64 + ejj][eb] + sbl[64 + ejj];
            float hprev = hs[p][eb][j0 + ejj];
            float r = 1.0f / (1.0f + __expf(-(xr + hr)));
            float z = 1.0f / (1.0f + __expf(-(xz + hz)));
            float n = tanhf(xn + r * hn);
            float hnew = (1.0f - z) * n + z * hprev;

            // push hnew into ALL 8 CTAs' hs[1-p] (including our own)
            uint32_t laddr = (uint32_t)__cvta_generic_to_shared(
                &hs[1 - p][eb][j0 + ejj]);
#pragma unroll
            for (int rk = 0; rk < 8; rk++) {
                uint32_t ra;
                asm volatile("mapa.shared::cluster.u32 %0, %1, %2;"
                             : "=r"(ra) : "r"(laddr), "r"(rk));
                asm volatile("st.shared::cluster.f32 [%0], %1;"
                             :: "r"(ra), "f"(hnew) : "memory");
            }
            if (t == 255)
                g_hT[(long)(cid * 4 + eb) * 256 + j0 + ejj] = hnew;
        }
        // cluster barrier: arrive has release, wait has acquire semantics —
        // peer hs[1-p] writes are visible to all CTAs next iteration.
        asm volatile("barrier.cluster.arrive.aligned;" ::: "memory");
        asm volatile("barrier.cluster.wait.aligned;"   ::: "memory");
    }
}

// ---------------- final fc1 + relu ----------------
__global__ void fc_kernel(const float* __restrict__ fc1b, float* __restrict__ out) {
    __shared__ float hsf[HIDD];
    const int b = blockIdx.x, j = threadIdx.x;
    hsf[j] = g_hT[b * HIDD + j];
    __syncthreads();
    float acc = 0.0f;
#pragma unroll 8
    for (int k = 0; k < HIDD; k++) acc += hsf[k] * g_fc1WT[k * HIDD + j];
    acc += fc1b[j];
    out[b * HIDD + j] = acc > 0.0f ? acc : 0.0f;
}

// ---------------- launcher: kernel launches ONLY ----------------
extern "C" void kernel_launch(void* const* d_in, const int* in_sizes, int n_in,
                              void* d_out, int out_size) {
    const int*   neighbors = (const int*)  d_in[0];
    const float* adj       = (const float*)d_in[1];
    const int*   cur_node  = (const int*)  d_in[2];
    const int*   edge_src  = (const int*)  d_in[3];
    const int*   edge_dst  = (const int*)  d_in[4];
    const float* edge_w    = (const float*)d_in[5];
    const float* emb       = (const float*)d_in[6];
    const float* Wg        = (const float*)d_in[7];
    const float* bg        = (const float*)d_in[8];
    const float* W1        = (const float*)d_in[9];
    const float* b1        = (const float*)d_in[10];
    const float* W2        = (const float*)d_in[11];
    const float* b2        = (const float*)d_in[12];
    const float* eps       = (const float*)d_in[13];
    const float* Wih       = (const float*)d_in[14];
    const float* Whh       = (const float*)d_in[15];
    const float* bih       = (const float*)d_in[16];
    const float* bhh       = (const float*)d_in[17];
    const float* fc1W      = (const float*)d_in[18];
    const float* fc1b      = (const float*)d_in[19];
    float* out = (float*)d_out;

    const int  MBL  = BATCHN * LSEQ;        // 16384
    const long SADJ = (long)LSEQ * LSEQ;
    const long SX   = (long)LSEQ * HIDD;

    // 1: weight prep
    prep_kernel<<<256, 256>>>(Wih, fc1W);
    // 2: gated zero
    zero_agg_kernel<<<2048, 256>>>(eps);
    // 3: gated support GEMM
    mma_gemm_kernel<<<dim3(2, (ENTITYN + 255) / 256, 1), 256>>>(
        SEL_EXT, emb, 0, SEL_EXT, Wg, 0, SEL_SUPPORT, nullptr, 0,
        nullptr, nullptr, eps, ENTITYN, 256, 256);
    // 4 (ncu-profiled slot): real W1 gather-GEMM
    mma_gemm_kernel<<<dim3(2, MBL / 256, 1), 256>>>(
        SEL_EXT, emb, 0, SEL_EXT, W1, 0, SEL_BUFA, nullptr, 0,
        nullptr, neighbors, nullptr, MBL, 256, 256);
    // 5: gated scatter
    scatter_kernel<<<4096, 256>>>(edge_src, edge_dst, edge_w, eps);
    // 6: bufB = adj @ bufA + b1
    mma_gemm_kernel<<<dim3(2, 1, 64), 256>>>(
        SEL_EXT, adj, SADJ, SEL_BUFA, nullptr, SX, SEL_BUFB, nullptr, SX,
        b1, nullptr, nullptr, 256, 256, 256);
    // 7: bufA = bufB @ W2
    mma_gemm_kernel<<<dim3(2, MBL / 256, 1), 256>>>(
        SEL_BUFB, nullptr, 0, SEL_EXT, W2, 0, SEL_BUFA, nullptr, 0,
        nullptr, nullptr, nullptr, MBL, 256, 256);
    // 8: bufB = adj @ bufA + b2
    mma_gemm_kernel<<<dim3(2, 1, 64), 256>>>(
        SEL_EXT, adj, SADJ, SEL_BUFA, nullptr, SX, SEL_BUFB, nullptr, SX,
        b2, nullptr, nullptr, 256, 256, 256);
    // 9: mix
    mix_kernel<<<2048, 256>>>(cur_node, bg, eps);
    // 10: xi = bufA @ WihT + bih
    mma_gemm_kernel<<<dim3(6, MBL / 256, 1), 256>>>(
        SEL_BUFA, nullptr, 0, SEL_WIHT, nullptr, 0, SEL_XI, nullptr, 0,
        bih, nullptr, nullptr, MBL, 768, 256);
    // 11: GRU recurrence: 16 clusters x 8 CTAs, DSMEM exchange
    gru_cluster_kernel<<<128, 384>>>(Whh, bhh);
    // 12: out = relu(hT @ fc1W^T + fc1b)
    fc_kernel<<<64, 256>>>(fc1b, out);
}

// round 17
// speedup vs baseline: 1.5300x; 1.5300x over previous
#include <cuda_runtime.h>
#include <cstdint>

#define ENTITYN 50000
#define EMBD    256
#define HIDD    256
#define BATCHN  64
#define LSEQ    256
#define NEDGE   800000

// ---------------- scratch (device globals: no allocation allowed) ----------------
__device__ float g_bufA[BATCHN * LSEQ * HIDD];
__device__ float g_bufB[BATCHN * LSEQ * HIDD];
__device__ float g_xi[BATCHN * LSEQ * 3 * HIDD];
__device__ float g_WihT[HIDD * 3 * HIDD];
__device__ float g_fc1WT[HIDD * HIDD];
__device__ float g_support[ENTITYN * HIDD];
__device__ float g_agg[ENTITYN * HIDD];
__device__ float g_hT[BATCHN * HIDD];
__device__ float g_hx[2][BATCHN][HIDD];
__device__ unsigned int g_sync[32 * 64];   // 256B-padded group counters (proven)

#define SEL_EXT     0
#define SEL_BUFA    1
#define SEL_BUFB    2
#define SEL_XI      3
#define SEL_WIHT    4
#define SEL_SUPPORT 5

__device__ __forceinline__ float* selptr(int s, const void* ext) {
    switch (s) {
        case SEL_BUFA:    return g_bufA;
        case SEL_BUFB:    return g_bufB;
        case SEL_XI:      return g_xi;
        case SEL_WIHT:    return g_WihT;
        case SEL_SUPPORT: return g_support;
        default:          return (float*)ext;
    }
}

__device__ __forceinline__ uint32_t f2tf32(float x) {
    uint32_t u;
    asm("cvt.rna.tf32.f32 %0, %1;" : "=r"(u) : "f"(x));
    return u;
}

__device__ __forceinline__ void mma_tf32(float* c, const uint32_t* a,
                                         uint32_t b0, uint32_t b1) {
    asm volatile(
        "mma.sync.aligned.m16n8k8.row.col.f32.tf32.tf32.f32 "
        "{%0,%1,%2,%3}, {%4,%5,%6,%7}, {%8,%9}, {%0,%1,%2,%3};"
        : "+f"(c[0]), "+f"(c[1]), "+f"(c[2]), "+f"(c[3])
        : "r"(a[0]), "r"(a[1]), "r"(a[2]), "r"(a[3]), "r"(b0), "r"(b1));
}

// f32x2 packed-FMA helpers (proven in R14)
__device__ __forceinline__ unsigned long long packf2(float x, float y) {
    unsigned long long r;
    asm("mov.b64 %0, {%1, %2};"
        : "=l"(r) : "r"(__float_as_uint(x)), "r"(__float_as_uint(y)));
    return r;
}

__device__ __forceinline__ void ffma2(unsigned long long& acc,
                                      unsigned long long a,
                                      unsigned long long b) {
    asm("fma.rn.f32x2 %0, %1, %2, %0;" : "+l"(acc) : "l"(a), "l"(b));
}

__device__ __forceinline__ float unpack_sum(unsigned long long v) {
    uint32_t lo, hi;
    asm("mov.b64 {%0, %1}, %2;" : "=r"(lo), "=r"(hi) : "l"(v));
    return __uint_as_float(lo) + __uint_as_float(hi);
}

// ---------------- weight prep ----------------
__global__ void prep_kernel(const float* __restrict__ Wih,
                            const float* __restrict__ fc1W) {
    int stride = gridDim.x * blockDim.x;
    int t0 = blockIdx.x * blockDim.x + threadIdx.x;
    for (int i = t0; i < 32 * 64; i += stride) g_sync[i] = 0u;
    for (int i = t0; i < 256 * 768; i += stride) {
        int k = i / 768, n = i % 768;
        g_WihT[i] = Wih[n * 256 + k];
    }
    for (int i = t0; i < 256 * 256; i += stride) {
        int k = i / 256, j = i % 256;
        g_fc1WT[i] = fc1W[j * 256 + k];
    }
}

// ---------------- gated GNN path ----------------
__global__ void zero_agg_kernel(const float* __restrict__ eps) {
    if (eps[0] == 0.0f) return;
    int stride = gridDim.x * blockDim.x;
    for (int i = blockIdx.x * blockDim.x + threadIdx.x; i < ENTITYN * HIDD; i += stride)
        g_agg[i] = 0.0f;
}

__global__ void scatter_kernel(const int* __restrict__ esrc,
                               const int* __restrict__ edst,
                               const float* __restrict__ ew,
                               const float* __restrict__ eps) {
    if (eps[0] == 0.0f) return;
    long stride = (long)gridDim.x * blockDim.x;
    long total = (long)NEDGE * 64;
    for (long i = (long)blockIdx.x * blockDim.x + threadIdx.x; i < total; i += stride) {
        int e = (int)(i >> 6);
        int c = ((int)i & 63) * 4;
        int s = esrc[e], d = edst[e];
        float w = ew[e];
        const float4 v = *(const float4*)&g_support[(long)s * 256 + c];
        float* dst = &g_agg[(long)d * 256 + c];
        atomicAdd(dst + 0, v.x * w);
        atomicAdd(dst + 1, v.y * w);
        atomicAdd(dst + 2, v.z * w);
        atomicAdd(dst + 3, v.w * w);
    }
}

// ---------------- tf32 GEMM: block 128x128, BK=16, double-buffered smem,
// 2 CTAs/SM. Warp tile 32x64 (R4/R10-proven mappings). Optional eps-based
// A-input select (epsSel: if eps==0 use selA2 instead of selA).
__global__ void __launch_bounds__(256, 2) mma_gemm_kernel(
    int selA, int selA2, const float* __restrict__ epsSel,
    const void* Aext, long strideA,
    int selB, const void* Bext, long strideB,
    int selC, void* Cext, long strideC,
    const float* __restrict__ bias,
    const int* __restrict__ gidx,
    const float* __restrict__ gate,
    int M, int N, int K)
{
    if (gate != nullptr && gate[0] == 0.0f) return;
    int sa = selA;
    if (epsSel != nullptr && epsSel[0] == 0.0f) sa = selA2;
    const float* A = selptr(sa, Aext) + (long)blockIdx.z * strideA;
    const float* B = selptr(selB, Bext) + (long)blockIdx.z * strideB;
    float*       C = selptr(selC, Cext) + (long)blockIdx.z * strideC;

    __shared__ uint32_t As[2][128][20];   // [buf][m][k], pad 20: conflict-free
    __shared__ uint32_t Bs[2][16][136];   // [buf][k][n], pad 136: conflict-free

    const int tid  = threadIdx.x;
    const int wid  = tid >> 5, lane = tid & 31;
    const int g    = lane >> 2, t = lane & 3;
    const int wm   = wid >> 1, wn = wid & 1;
    const int m0   = blockIdx.y * 128, n0 = blockIdx.x * 128;

    // A staging: 128 rows x 16 k = 512 float4; 2 per thread
    long agrow[2];
#pragma unroll
    for (int i = 0; i < 2; i++) {
        int f = tid + i * 256;
        int m = m0 + (f >> 2);
        agrow[i] = (m < M) ? (gidx ? (long)gidx[m] : (long)m) : -1;
    }

    float acc[2][8][4];
#pragma unroll
    for (int mt = 0; mt < 2; mt++)
#pragma unroll
        for (int nt = 0; nt < 8; nt++)
#pragma unroll
            for (int q = 0; q < 4; q++) acc[mt][nt][q] = 0.0f;

    const int NCH = K >> 4;
    float4 ar[2], br[2];

    // preload chunk 0 into regs, stage into buffer 0
#pragma unroll
    for (int i = 0; i < 2; i++) {
        int f = tid + i * 256;
        int kc = (f & 3) * 4;
        ar[i] = (agrow[i] >= 0) ? *(const float4*)(A + agrow[i] * K + kc)
                                : make_float4(0.f, 0.f, 0.f, 0.f);
    }
#pragma unroll
    for (int i = 0; i < 2; i++) {
        int f = tid + i * 256;
        int kk = f >> 5, n4 = (f & 31) * 4;
        br[i] = *(const float4*)(B + (long)kk * N + n0 + n4);
    }
#pragma unroll
    for (int i = 0; i < 2; i++) {
        int f = tid + i * 256;
        int row = f >> 2, kc = (f & 3) * 4;
        uint4 u = make_uint4(f2tf32(ar[i].x), f2tf32(ar[i].y),
                             f2tf32(ar[i].z), f2tf32(ar[i].w));
        *(uint4*)&As[0][row][kc] = u;
    }
#pragma unroll
    for (int i = 0; i < 2; i++) {
        int f = tid + i * 256;
        int kk = f >> 5, n4 = (f & 31) * 4;
        uint4 u = make_uint4(f2tf32(br[i].x), f2tf32(br[i].y),
                             f2tf32(br[i].z), f2tf32(br[i].w));
        *(uint4*)&Bs[0][kk][n4] = u;
    }
    __syncthreads();

    for (int c = 0; c < NCH; c++) {
        const int cur = c & 1;
        // prefetch next chunk into regs (overlaps mma below)
        if (c + 1 < NCH) {
            int k0n = (c + 1) * 16;
#pragma unroll
            for (int i = 0; i < 2; i++) {
                int f = tid + i * 256;
                int kc = (f & 3) * 4;
                ar[i] = (agrow[i] >= 0)
                        ? *(const float4*)(A + agrow[i] * K + k0n + kc)
                        : make_float4(0.f, 0.f, 0.f, 0.f);
            }
#pragma unroll
            for (int i = 0; i < 2; i++) {
                int f = tid + i * 256;
                int kk = f >> 5, n4 = (f & 31) * 4;
                br[i] = *(const float4*)(B + (long)(k0n + kk) * N + n0 + n4);
            }
        }

#pragma unroll
        for (int ks = 0; ks < 16; ks += 8) {
            uint32_t af[2][4];
#pragma unroll
            for (int mt = 0; mt < 2; mt++) {
                int r = wm * 32 + mt * 16 + g;
                af[mt][0] = As[cur][r    ][ks + t];
                af[mt][1] = As[cur][r + 8][ks + t];
                af[mt][2] = As[cur][r    ][ks + t + 4];
                af[mt][3] = As[cur][r + 8][ks + t + 4];
            }
#pragma unroll
            for (int nt = 0; nt < 8; nt++) {
                int cc = wn * 64 + nt * 8 + g;
                uint32_t b0 = Bs[cur][ks + t    ][cc];
                uint32_t b1 = Bs[cur][ks + t + 4][cc];
                mma_tf32(acc[0][nt], af[0], b0, b1);
                mma_tf32(acc[1][nt], af[1], b0, b1);
            }
        }

        // stage next chunk into the other buffer (mma above read 'cur')
        if (c + 1 < NCH) {
            const int nxt = 1 - cur;
#pragma unroll
            for (int i = 0; i < 2; i++) {
                int f = tid + i * 256;
                int row = f >> 2, kc = (f & 3) * 4;
                uint4 u = make_uint4(f2tf32(ar[i].x), f2tf32(ar[i].y),
                                     f2tf32(ar[i].z), f2tf32(ar[i].w));
                *(uint4*)&As[nxt][row][kc] = u;
            }
#pragma unroll
            for (int i = 0; i < 2; i++) {
                int f = tid + i * 256;
                int kk = f >> 5, n4 = (f & 31) * 4;
                uint4 u = make_uint4(f2tf32(br[i].x), f2tf32(br[i].y),
                                     f2tf32(br[i].z), f2tf32(br[i].w));
                *(uint4*)&Bs[nxt][kk][n4] = u;
            }
        }
        __syncthreads();
    }

    // epilogue (proven mapping)
#pragma unroll
    for (int mt = 0; mt < 2; mt++) {
        int r0 = m0 + wm * 32 + mt * 16 + g;
#pragma unroll
        for (int nt = 0; nt < 8; nt++) {
            int cc = n0 + wn * 64 + nt * 8 + 2 * t;
            float b0v = 0.f, b1v = 0.f;
            if (bias) { b0v = bias[cc]; b1v = bias[cc + 1]; }
            if (r0 < M) {
                float2 o = make_float2(acc[mt][nt][0] + b0v, acc[mt][nt][1] + b1v);
                *(float2*)(C + (long)r0 * N + cc) = o;
            }
            int r1 = r0 + 8;
            if (r1 < M) {
                float2 o = make_float2(acc[mt][nt][2] + b0v, acc[mt][nt][3] + b1v);
                *(float2*)(C + (long)r1 * N + cc) = o;
            }
        }
    }
}

// ---------------- eps mix: gated — runs ONLY when eps != 0 (GEMM 10 reads
// bufB directly when eps == 0 via its input select) ----------------
__global__ void mix_kernel(const int* __restrict__ cur,
                           const float* __restrict__ bg,
                           const float* __restrict__ eps) {
    float e = eps[0];
    if (e == 0.0f) return;
    int stride = gridDim.x * blockDim.x;
    for (int i = blockIdx.x * blockDim.x + threadIdx.x; i < BATCHN * LSEQ * HIDD; i += stride) {
        int row = i >> 8, col = i & 255;
        int cn = cur[row];
        float a = g_agg[(long)cn * 256 + col] + bg[col];
        a = a > 0.0f ? a : 0.2f * a;
        g_bufA[i] = (1.0f - e) * g_bufB[i] + e * a;
    }
}

// ---------------- GRU (byte-identical to R14-passing version) ----------------
__global__ void __launch_bounds__(384, 1)
gru_sync_kernel(const float* __restrict__ Whh,
                const float* __restrict__ bhh,
                int nsteps, int syncbase) {
    __shared__ __align__(16) float hs[4][256];
    __shared__ float gh[96][4];
    __shared__ float sbl[96];

    const int tid  = threadIdx.x;
    const int cid  = blockIdx.x >> 3;
    const int rank = blockIdx.x & 7;
    const int j0   = rank * 32;

    const int lrow = tid >> 2;
    const int kq   = tid & 3;
    const int gate = lrow >> 5;
    const int jj   = lrow & 31;
    const int grow = gate * 256 + j0 + jj;

    unsigned long long w2[32];
    {
        const float* wrow = Whh + (long)grow * 256;
#pragma unroll
        for (int k4 = 0; k4 < 16; k4++) {
            float4 v = *(const float4*)(wrow + k4 * 16 + kq * 4);
            w2[k4 * 2 + 0] = packf2(v.x, v.y);
            w2[k4 * 2 + 1] = packf2(v.z, v.w);
        }
    }
    if (tid < 96) sbl[tid] = bhh[(tid >> 5) * 256 + j0 + (tid & 31)];

    const int ejj = tid >> 2, eb = tid & 3;
    unsigned int* cnt = &g_sync[(syncbase + cid) * 64];

    if (tid < 128)
        __stcg(&g_hx[0][cid * 4 + eb][j0 + ejj], 0.0f);
    __syncthreads();
    if (tid == 0)
        asm volatile("red.release.gpu.global.add.u32 [%0], %1;"
                     :: "l"(cnt), "r"(1u) : "memory");

    for (int t = 0; t < nsteps; t++) {
        const int p = t & 1;
        float xr = 0.f, xz = 0.f, xn = 0.f;
        if (tid < 128) {
            const float* xb = g_xi + (((long)(cid * 4 + eb) * 256 + t) * 768);
            xr = xb[j0 + ejj];
            xz = xb[256 + j0 + ejj];
            xn = xb[512 + j0 + ejj];
        }
        if (tid == 0) {
            const unsigned int target = 8u * (unsigned)(t + 1);
            unsigned int v;
            do {
                asm volatile("ld.global.acquire.gpu.u32 %0, [%1];"
                             : "=r"(v) : "l"(cnt));
            } while (v < target);
        }
        __syncthreads();

        if (tid < 256) {
            const float4* src = (const float4*)&g_hx[p][cid * 4][0];
            ((float4*)hs)[tid] = __ldcg(src + tid);
        }
        __syncthreads();

        unsigned long long a2[4] = {0ull, 0ull, 0ull, 0ull};
#pragma unroll
        for (int k4 = 0; k4 < 16; k4++) {
            const int ko = k4 * 16 + kq * 4;
            ulonglong2 h0 = *(const ulonglong2*)&hs[0][ko];
            ulonglong2 h1 = *(const ulonglong2*)&hs[1][ko];
            ulonglong2 h2 = *(const ulonglong2*)&hs[2][ko];
            ulonglong2 h3 = *(const ulonglong2*)&hs[3][ko];
            unsigned long long wa = w2[k4 * 2], wb = w2[k4 * 2 + 1];
            ffma2(a2[0], wa, h0.x); ffma2(a2[0], wb, h0.y);
            ffma2(a2[1], wa, h1.x); ffma2(a2[1], wb, h1.y);
            ffma2(a2[2], wa, h2.x); ffma2(a2[2], wb, h2.y);
            ffma2(a2[3], wa, h3.x); ffma2(a2[3], wb, h3.y);
        }
        float acc0 = unpack_sum(a2[0]);
        float acc1 = unpack_sum(a2[1]);
        float acc2 = unpack_sum(a2[2]);
        float acc3 = unpack_sum(a2[3]);
        acc0 += __shfl_xor_sync(0xFFFFFFFFu, acc0, 1);
        acc0 += __shfl_xor_sync(0xFFFFFFFFu, acc0, 2);
        acc1 += __shfl_xor_sync(0xFFFFFFFFu, acc1, 1);
        acc1 += __shfl_xor_sync(0xFFFFFFFFu, acc1, 2);
        acc2 += __shfl_xor_sync(0xFFFFFFFFu, acc2, 1);
        acc2 += __shfl_xor_sync(0xFFFFFFFFu, acc2, 2);
        acc3 += __shfl_xor_sync(0xFFFFFFFFu, acc3, 1);
        acc3 += __shfl_xor_sync(0xFFFFFFFFu, acc3, 2);
        if (kq == 0) {
            gh[lrow][0] = acc0; gh[lrow][1] = acc1;
            gh[lrow][2] = acc2; gh[lrow][3] = acc3;
        }
        __syncthreads();

        if (tid < 128) {
            float hr = gh[ejj][eb]      + sbl[ejj];
            float hz = gh[32 + ejj][eb] + sbl[32 + ejj];
            float hn = gh[64 + ejj][eb] + sbl[64 + ejj];
            float hprev = hs[eb][j0 + ejj];
            float r = 1.0f / (1.0f + __expf(-(xr + hr)));
            float z = 1.0f / (1.0f + __expf(-(xz + hz)));
            float n = tanhf(xn + r * hn);
            float hnew = (1.0f - z) * n + z * hprev;

            __stcg(&g_hx[1 - p][cid * 4 + eb][j0 + ejj], hnew);
            if (t == nsteps - 1)
                g_hT[(long)(cid * 4 + eb) * 256 + j0 + ejj] = hnew;
        }
        __syncthreads();
        if (tid == 0)
            asm volatile("red.release.gpu.global.add.u32 [%0], %1;"
                         :: "l"(cnt), "r"(1u) : "memory");
    }
}

// ---------------- final fc1 + relu ----------------
__global__ void fc_kernel(const float* __restrict__ fc1b, float* __restrict__ out) {
    __shared__ float hsf[HIDD];
    const int b = blockIdx.x, j = threadIdx.x;
    hsf[j] = g_hT[b * HIDD + j];
    __syncthreads();
    float acc = 0.0f;
#pragma unroll 8
    for (int k = 0; k < HIDD; k++) acc += hsf[k] * g_fc1WT[k * HIDD + j];
    acc += fc1b[j];
    out[b * HIDD + j] = acc > 0.0f ? acc : 0.0f;
}

// ---------------- launcher: kernel launches ONLY ----------------
extern "C" void kernel_launch(void* const* d_in, const int* in_sizes, int n_in,
                              void* d_out, int out_size) {
    const int*   neighbors = (const int*)  d_in[0];
    const float* adj       = (const float*)d_in[1];
    const int*   cur_node  = (const int*)  d_in[2];
    const int*   edge_src  = (const int*)  d_in[3];
    const int*   edge_dst  = (const int*)  d_in[4];
    const float* edge_w    = (const float*)d_in[5];
    const float* emb       = (const float*)d_in[6];
    const float* Wg        = (const float*)d_in[7];
    const float* bg        = (const float*)d_in[8];
    const float* W1        = (const float*)d_in[9];
    const float* b1        = (const float*)d_in[10];
    const float* W2        = (const float*)d_in[11];
    const float* b2        = (const float*)d_in[12];
    const float* eps       = (const float*)d_in[13];
    const float* Wih       = (const float*)d_in[14];
    const float* Whh       = (const float*)d_in[15];
    const float* bih       = (const float*)d_in[16];
    const float* bhh       = (const float*)d_in[17];
    const float* fc1W      = (const float*)d_in[18];
    const float* fc1b      = (const float*)d_in[19];
    float* out = (float*)d_out;

    const int  MBL  = BATCHN * LSEQ;        // 16384
    const long SADJ = (long)LSEQ * LSEQ;
    const long SX   = (long)LSEQ * HIDD;

    // 1: weight prep + counter reset
    prep_kernel<<<256, 256>>>(Wih, fc1W);
    // 2: gated zero
    zero_agg_kernel<<<2048, 256>>>(eps);
    // 3: gated support GEMM
    mma_gemm_kernel<<<dim3(2, (ENTITYN + 127) / 128, 1), 256>>>(
        SEL_EXT, SEL_EXT, nullptr, emb, 0, SEL_EXT, Wg, 0,
        SEL_SUPPORT, nullptr, 0, nullptr, nullptr, eps, ENTITYN, 256, 256);
    // 4 (ncu-profiled slot): real W1 gather-GEMM
    mma_gemm_kernel<<<dim3(2, MBL / 128, 1), 256>>>(
        SEL_EXT, SEL_EXT, nullptr, emb, 0, SEL_EXT, W1, 0,
        SEL_BUFA, nullptr, 0, nullptr, neighbors, nullptr, MBL, 256, 256);
    // 5: gated scatter
    scatter_kernel<<<4096, 256>>>(edge_src, edge_dst, edge_w, eps);
    // 6: bufB = adj @ bufA + b1
    mma_gemm_kernel<<<dim3(2, 2, 64), 256>>>(
        SEL_EXT, SEL_EXT, nullptr, adj, SADJ, SEL_BUFA, nullptr, SX,
        SEL_BUFB, nullptr, SX, b1, nullptr, nullptr, 256, 256, 256);
    // 7: bufA = bufB @ W2
    mma_gemm_kernel<<<dim3(2, MBL / 128, 1), 256>>>(
        SEL_BUFB, SEL_BUFB, nullptr, nullptr, 0, SEL_EXT, W2, 0,
        SEL_BUFA, nullptr, 0, nullptr, nullptr, nullptr, MBL, 256, 256);
    // 8: bufB = adj @ bufA + b2
    mma_gemm_kernel<<<dim3(2, 2, 64), 256>>>(
        SEL_EXT, SEL_EXT, nullptr, adj, SADJ, SEL_BUFA, nullptr, SX,
        SEL_BUFB, nullptr, SX, b2, nullptr, nullptr, 256, 256, 256);
    // 9: mix (runs only when eps != 0)
    mix_kernel<<<2048, 256>>>(cur_node, bg, eps);
    // 10: xi = (eps==0 ? bufB : bufA) @ WihT + bih  — device-side select
    mma_gemm_kernel<<<dim3(6, MBL / 128, 1), 256>>>(
        SEL_BUFA, SEL_BUFB, eps, nullptr, 0, SEL_WIHT, nullptr, 0,
        SEL_XI, nullptr, 0, bih, nullptr, nullptr, MBL, 768, 256);
    // 11: GRU recurrence (R14-proven)
    gru_sync_kernel<<<128, 384>>>(Whh, bhh, 256, 0);
    // 12: out = relu(hT @ fc1W^T + fc1b)
    fc_kernel<<<64, 256>>>(fc1b, out);
}